// round 7
// baseline (speedup 1.0000x reference)
#include <cuda_runtime.h>
#include <cuda_bf16.h>
#include <cstdint>

// Problem shape (fixed by setup_inputs): preds [T,B,C] f32, targets [B,L] i64.
#define TT 128
#define BB 128
#define CC 8192
#define LL 50
#define NSLOT 51   // slot 0 = blank, slots 1..50 = labels

// Scratch (zero at module load; finishers restore zeros every call, and the
// kernel-launch boundary orders those stores before the next graph replay).
__device__ float    g_acc[BB * NSLOT];   // per-(b,slot) sum_t exp(x)/Z
__device__ unsigned g_cnt[BB];           // per-b arrival counters
__device__ float    g_loss;              // global loss accumulator
__device__ unsigned g_cnt2;              // global finisher counter

// Fast exp on the FMA pipe (no MUFU). Add-magic rounding + degree-4 poly
// for 2^f on f in [-0.5, 0.5]. Rel err ~5e-5.
__device__ __forceinline__ float fast_exp(float x) {
    const float L2E = 1.4426950408889634f;
    float t  = fmaf(x, L2E, 12582912.0f);
    float nf = t - 12582912.0f;
    float f  = fmaf(x, L2E, -nf);
    int   ni = __float_as_int(t) - 0x4B400000;
    float sc = __int_as_float((ni << 23) + 0x3F800000);
    float p = fmaf(f, 0.009618129f, 0.05550411f);
    p = fmaf(f, p, 0.2402265f);
    p = fmaf(f, p, 0.6931472f);
    float fp = f * p;
    return fmaf(fp, sc, sc);
}

// Counter bump with acq_rel semantics: releases this thread's (and, via the
// preceding __syncthreads, the block's) prior memory ops; acquires for the
// winner. Native coherence bits on ATOMG -- no MEMBAR, no CCTL.IVALL.
__device__ __forceinline__ unsigned atom_inc_acq_rel(unsigned* p) {
    unsigned r;
    asm volatile("atom.acq_rel.gpu.global.add.u32 %0, [%1], 1;"
                 : "=r"(r) : "l"(p) : "memory");
    return r;
}

// ---------------------------------------------------------------------------
// Single kernel. One block per (t,b) row: stream 32 KB -> Z; 51 L1-hit
// gathers; 51 relaxed REDG adds into dense g_acc[b][*]. Last block per b
// (acq_rel counter) computes weights/logs -> g_loss; globally-last block
// writes *out and resets all scratch. No fences anywhere.
// ---------------------------------------------------------------------------
__global__ __launch_bounds__(256) void ace_kernel(
    const float* __restrict__ preds,
    const long long* __restrict__ tgt,
    float* __restrict__ out)
{
    int tb  = blockIdx.x;                 // = t*BB + b
    int b   = tb & (BB - 1);
    int tid = threadIdx.x;

    // Prefetch label (latency hidden under the 32 KB stream below).
    int   c    = 0;                       // slot 0 -> blank class 0
    float wpos = 0.0f;
    if (tid >= 1 && tid < NSLOT) {
        long long l = tgt[(size_t)b * LL + (tid - 1)];
        if (l > 0 && l < CC) { c = (int)l; wpos = 1.0f; }
    }

    const float* rowf = preds + (size_t)tb * CC;
    const float4* row = reinterpret_cast<const float4*>(rowf);
    float acc = 0.0f;
#pragma unroll
    for (int i = 0; i < 8; i++) {
        float4 v = row[tid + i * 256];    // 8 front-batched LDG.128
        acc += fast_exp(v.x) + fast_exp(v.y) + fast_exp(v.z) + fast_exp(v.w);
    }
#pragma unroll
    for (int o = 16; o > 0; o >>= 1)
        acc += __shfl_xor_sync(0xFFFFFFFFu, acc, o);

    __shared__ float    s[8];
    __shared__ unsigned s_rank;
    if ((tid & 31) == 0) s[tid >> 5] = acc;
    __syncthreads();

    if (tid < NSLOT) {
        float z = s[0] + s[1] + s[2] + s[3] + s[4] + s[5] + s[6] + s[7];
        float invz = 1.0f / z;
        // L1-hit gather (row just streamed) -> relaxed REDG into L2 scratch.
        atomicAdd(&g_acc[b * NSLOT + tid], fast_exp(rowf[c]) * invz);
    }

    __syncthreads();                      // block's REDGs precede the counter
    if (tid == 0) s_rank = atom_inc_acq_rel(&g_cnt[b]);
    __syncthreads();
    if (s_rank != TT - 1) return;

    // ---- per-b finisher (last arriving block for this b) ----
    // npos = # valid positive labels (reduce wpos over tids 1..50).
    float f = wpos;
#pragma unroll
    for (int o = 16; o > 0; o >>= 1)
        f += __shfl_xor_sync(0xFFFFFFFFu, f, o);
    __shared__ float sw[2];
    if (tid == 0 || tid == 32) sw[tid >> 5] = f;
    __syncthreads();
    float npos = sw[0] + sw[1];
    __syncthreads();

    const float LOG_T = 4.852030263919617f;    // ln(128)
    float contrib = 0.0f;
    if (tid < NSLOT) {
        float total = __ldcg(&g_acc[b * NSLOT + tid]);  // L2 (acquire chain)
        g_acc[b * NSLOT + tid] = 0.0f;                  // restore invariant
        float w = (tid == 0) ? ((float)TT - npos) : wpos;
        if (w != 0.0f) contrib = w * (__logf(total) - LOG_T);
    }
#pragma unroll
    for (int o = 16; o > 0; o >>= 1)
        contrib += __shfl_xor_sync(0xFFFFFFFFu, contrib, o);
    __syncthreads();
    if (tid == 0 || tid == 32) sw[tid >> 5] = contrib;
    __syncthreads();

    if (tid == 0) {
        g_cnt[b] = 0;                          // restore invariant
        atomicAdd(&g_loss, sw[0] + sw[1]);     // relaxed; released by g_cnt2
        if (atom_inc_acq_rel(&g_cnt2) == BB - 1) {
            // ---- global finisher ----
            float tl = __ldcg(&g_loss);
            *out = -tl * (1.0f / ((float)BB * (float)TT));
            g_loss = 0.0f;                     // restore invariants
            g_cnt2 = 0u;
        }
    }
}

extern "C" void kernel_launch(void* const* d_in, const int* in_sizes, int n_in,
                              void* d_out, int out_size)
{
    const float*     preds = (const float*)d_in[0];
    const long long* tgt   = (const long long*)d_in[1];
    float*           out   = (float*)d_out;

    ace_kernel<<<TT * BB, 256>>>(preds, tgt, out);
}

// round 8
// speedup vs baseline: 1.0411x; 1.0411x over previous
#include <cuda_runtime.h>
#include <cuda_bf16.h>
#include <cstdint>

// Problem shape (fixed by setup_inputs): preds [T,B,C] f32, targets [B,L] i64.
#define TT 128
#define BB 128
#define CC 8192
#define LL 50
#define NSLOT 51        // slot 0 = blank, slots 1..50 = labels
#define NSTREAM (TT*BB) // 16384 streaming blocks; finishers follow

// Scratch (zero at module load; finishers restore zeros every call; the
// launch boundary orders those stores before the next graph replay).
__device__ float    g_acc[BB * NSLOT];   // per-(b,slot) sum_t exp(x)/Z
__device__ unsigned g_cnt[BB];           // per-b arrival counters
__device__ float    g_loss;              // global loss accumulator
__device__ unsigned g_cnt2;              // global finisher counter

// Fast exp on the FMA pipe (no MUFU). Rel err ~5e-5.
__device__ __forceinline__ float fast_exp(float x) {
    const float L2E = 1.4426950408889634f;
    float t  = fmaf(x, L2E, 12582912.0f);
    float nf = t - 12582912.0f;
    float f  = fmaf(x, L2E, -nf);
    int   ni = __float_as_int(t) - 0x4B400000;
    float sc = __int_as_float((ni << 23) + 0x3F800000);
    float p = fmaf(f, 0.009618129f, 0.05550411f);
    p = fmaf(f, p, 0.2402265f);
    p = fmaf(f, p, 0.6931472f);
    float fp = f * p;
    return fmaf(fp, sc, sc);
}

// Fire-and-forget release add: no return value, no wait, orders the block's
// prior REDGs (via the preceding __syncthreads) before the counter bump.
__device__ __forceinline__ void red_release_add(unsigned* p, unsigned v) {
    asm volatile("red.release.gpu.global.add.u32 [%0], %1;"
                 :: "l"(p), "r"(v) : "memory");
}
__device__ __forceinline__ unsigned ld_relaxed(const unsigned* p) {
    unsigned r;
    asm volatile("ld.relaxed.gpu.global.u32 %0, [%1];" : "=r"(r) : "l"(p) : "memory");
    return r;
}
__device__ __forceinline__ unsigned ld_acquire(const unsigned* p) {
    unsigned r;
    asm volatile("ld.acquire.gpu.global.u32 %0, [%1];" : "=r"(r) : "l"(p) : "memory");
    return r;
}

// ---------------------------------------------------------------------------
// Blocks [0, NSTREAM): stream row (t,b) -> Z; 51 L1-hit gathers; 51 relaxed
// REDG adds; one release-red on g_cnt[b]. Nothing waits.
// Blocks [NSTREAM, NSTREAM+BB): per-b finishers (spin, acquire, logs);
// finisher b==0 additionally writes *out and resets globals.
// ---------------------------------------------------------------------------
__global__ __launch_bounds__(256) void ace_kernel(
    const float* __restrict__ preds,
    const long long* __restrict__ tgt,
    float* __restrict__ out)
{
    int blk = blockIdx.x;
    int tid = threadIdx.x;

    if (blk < NSTREAM) {
        // ================= streaming path (identical to R5 zsum) ==========
        int b = blk & (BB - 1);

        // Prefetch label (latency hidden under the 32 KB stream).
        int c = 0;                        // slot 0 -> blank class 0
        if (tid >= 1 && tid < NSLOT) {
            long long l = tgt[(size_t)b * LL + (tid - 1)];
            if (l > 0 && l < CC) c = (int)l;
        }

        const float* rowf = preds + (size_t)blk * CC;
        const float4* row = reinterpret_cast<const float4*>(rowf);
        float acc = 0.0f;
#pragma unroll
        for (int i = 0; i < 8; i++) {
            float4 v = row[tid + i * 256];    // 8 front-batched LDG.128
            acc += fast_exp(v.x) + fast_exp(v.y) + fast_exp(v.z) + fast_exp(v.w);
        }
#pragma unroll
        for (int o = 16; o > 0; o >>= 1)
            acc += __shfl_xor_sync(0xFFFFFFFFu, acc, o);

        __shared__ float s[8];
        if ((tid & 31) == 0) s[tid >> 5] = acc;
        __syncthreads();

        if (tid < NSLOT) {
            float z = s[0] + s[1] + s[2] + s[3] + s[4] + s[5] + s[6] + s[7];
            float invz = 1.0f / z;
            atomicAdd(&g_acc[b * NSLOT + tid], fast_exp(rowf[c]) * invz);
        }

        __syncthreads();                  // block's REDGs precede the release
        if (tid == 0) red_release_add(&g_cnt[b], 1u);
        return;
    }

    // ===================== finisher path ==================================
    int b = blk - NSTREAM;

    // Prefetch labels while the stream drains.
    float wpos = 0.0f;
    if (tid >= 1 && tid < NSLOT) {
        long long l = tgt[(size_t)b * LL + (tid - 1)];
        wpos = (l > 0 && l < CC) ? 1.0f : 0.0f;
    }
    // npos reduce (first 2 warps cover tids 0..63; others contribute 0).
    __shared__ float sw[8];
    float f = wpos;
#pragma unroll
    for (int o = 16; o > 0; o >>= 1)
        f += __shfl_xor_sync(0xFFFFFFFFu, f, o);
    if ((tid & 31) == 0) sw[tid >> 5] = f;
    __syncthreads();
    float npos = sw[0] + sw[1];
    __syncthreads();

    // Wait for all 128 t-blocks of this b.
    if (tid == 0) {
        while (ld_relaxed(&g_cnt[b]) < TT) __nanosleep(64);
        (void)ld_acquire(&g_cnt[b]);      // sync with the release sequence
    }
    __syncthreads();

    const float LOG_T = 4.852030263919617f;    // ln(128)
    float contrib = 0.0f;
    if (tid < NSLOT) {
        float total = __ldcg(&g_acc[b * NSLOT + tid]);   // L2, bypass L1
        g_acc[b * NSLOT + tid] = 0.0f;                   // restore invariant
        float w = (tid == 0) ? ((float)TT - npos) : wpos;
        if (w != 0.0f) contrib = w * (__logf(total) - LOG_T);
    }
#pragma unroll
    for (int o = 16; o > 0; o >>= 1)
        contrib += __shfl_xor_sync(0xFFFFFFFFu, contrib, o);
    __syncthreads();
    if ((tid & 31) == 0) sw[tid >> 5] = contrib;
    __syncthreads();

    if (tid == 0) {
        g_cnt[b] = 0;                               // restore invariant
        atomicAdd(&g_loss, sw[0] + sw[1]);          // relaxed REDG
        red_release_add(&g_cnt2, 1u);
        if (b == 0) {
            while (ld_relaxed(&g_cnt2) < BB) __nanosleep(64);
            (void)ld_acquire(&g_cnt2);
            float tl = __ldcg(&g_loss);
            *out = -tl * (1.0f / ((float)BB * (float)TT));
            g_loss = 0.0f;                          // restore invariants
            g_cnt2 = 0u;
        }
    }
}

extern "C" void kernel_launch(void* const* d_in, const int* in_sizes, int n_in,
                              void* d_out, int out_size)
{
    const float*     preds = (const float*)d_in[0];
    const long long* tgt   = (const long long*)d_in[1];
    float*           out   = (float*)d_out;

    ace_kernel<<<NSTREAM + BB, 256>>>(preds, tgt, out);
}

// round 9
// speedup vs baseline: 1.0416x; 1.0004x over previous
#include <cuda_runtime.h>
#include <cuda_bf16.h>
#include <cstdint>

// Problem shape (fixed by setup_inputs): preds [T,B,C] f32, targets [B,L] i64.
#define TT 128
#define BB 128
#define CC 8192
#define LL 50
#define NSLOT 51   // slot 0 = blank, slots 1..50 = labels

// Scratch. g_acc: zero at load; finish re-zeroes after reading (replay
// invariant). g_w: fully overwritten every call by tp==63 blocks.
__device__ float g_acc[BB * NSLOT];   // per-(b,slot) sum_t exp(x)/Z
__device__ float g_w[BB * NSLOT];     // per-(b,slot) weight (0/1), slot0=0

// Fast exp on the FMA pipe (no MUFU). Rel err ~5e-5.
__device__ __forceinline__ float fast_exp(float x) {
    const float L2E = 1.4426950408889634f;
    float t  = fmaf(x, L2E, 12582912.0f);
    float nf = t - 12582912.0f;
    float f  = fmaf(x, L2E, -nf);
    int   ni = __float_as_int(t) - 0x4B400000;
    float sc = __int_as_float((ni << 23) + 0x3F800000);
    float p = fmaf(f, 0.009618129f, 0.05550411f);
    p = fmaf(f, p, 0.2402265f);
    p = fmaf(f, p, 0.6931472f);
    float fp = f * p;
    return fmaf(fp, sc, sc);
}

// ---------------------------------------------------------------------------
// Kernel 1: one block per (t-pair, b). Streams rows (t=tp, b) and (t=tp+64, b)
// sequentially (both stay L1-resident), computes both Z's, gathers the 51
// sparse classes from both rows, and issues ONE combined REDG per slot.
// tp==63 blocks additionally dump per-slot weights to g_w (L2-hot for k2).
// ---------------------------------------------------------------------------
__global__ __launch_bounds__(256, 6) void zsum_kernel(
    const float* __restrict__ preds,
    const long long* __restrict__ tgt,
    float* __restrict__ out)
{
    int blk = blockIdx.x;                 // = tp*BB + b, tp in [0,64)
    int b   = blk & (BB - 1);
    int tp  = blk >> 7;
    int tid = threadIdx.x;
    if (blk == 0 && tid == 0) *out = 0.0f;

    // Prefetch label (latency hidden under the 64 KB stream below).
    int   c    = 0;                       // slot 0 -> blank class 0
    float wpos = 0.0f;
    if (tid >= 1 && tid < NSLOT) {
        long long l = tgt[(size_t)b * LL + (tid - 1)];
        if (l > 0 && l < CC) { c = (int)l; wpos = 1.0f; }
    }

    const float* rowA = preds + ((size_t)tp * BB + b) * CC;          // t = tp
    const float* rowB = preds + ((size_t)(tp + 64) * BB + b) * CC;   // t = tp+64

    const float4* rA = reinterpret_cast<const float4*>(rowA);
    float accA = 0.0f;
#pragma unroll
    for (int i = 0; i < 8; i++) {
        float4 v = rA[tid + i * 256];     // 8 front-batched LDG.128
        accA += fast_exp(v.x) + fast_exp(v.y) + fast_exp(v.z) + fast_exp(v.w);
    }
    const float4* rB = reinterpret_cast<const float4*>(rowB);
    float accB = 0.0f;
#pragma unroll
    for (int i = 0; i < 8; i++) {
        float4 v = rB[tid + i * 256];
        accB += fast_exp(v.x) + fast_exp(v.y) + fast_exp(v.z) + fast_exp(v.w);
    }

#pragma unroll
    for (int o = 16; o > 0; o >>= 1) {
        accA += __shfl_xor_sync(0xFFFFFFFFu, accA, o);
        accB += __shfl_xor_sync(0xFFFFFFFFu, accB, o);
    }

    __shared__ float s[16];
    if ((tid & 31) == 0) { s[tid >> 5] = accA; s[8 + (tid >> 5)] = accB; }
    __syncthreads();

    if (tid < NSLOT) {
        float zA = s[0] + s[1] + s[2] + s[3] + s[4] + s[5] + s[6] + s[7];
        float zB = s[8] + s[9] + s[10] + s[11] + s[12] + s[13] + s[14] + s[15];
        // Both gathers are L1 hits (rows just streamed). One REDG for both t.
        float val = fast_exp(rowA[c]) * (1.0f / zA)
                  + fast_exp(rowB[c]) * (1.0f / zB);
        atomicAdd(&g_acc[b * NSLOT + tid], val);
        if (tp == 63) g_w[b * NSLOT + tid] = wpos;   // L2-hot for kernel 2
    }
}

// ---------------------------------------------------------------------------
// Kernel 2: tiny. One block per b, 64 threads. Everything it reads (g_acc,
// g_w) is L2-hot -- no DRAM on the critical path. Zeroes g_acc behind itself.
// ---------------------------------------------------------------------------
__global__ __launch_bounds__(64) void finish_kernel(float* __restrict__ out)
{
    int b   = blockIdx.x;
    int tid = threadIdx.x;

    float total = 0.0f, wpos = 0.0f;
    if (tid < NSLOT) {
        total = g_acc[b * NSLOT + tid];
        g_acc[b * NSLOT + tid] = 0.0f;     // restore invariant for next replay
        wpos  = g_w[b * NSLOT + tid];      // slot 0 reads 0
    }

    // npos = sum of wpos over the block (2 warps).
    __shared__ float sw[2];
    float f = wpos;
#pragma unroll
    for (int o = 16; o > 0; o >>= 1)
        f += __shfl_xor_sync(0xFFFFFFFFu, f, o);
    if ((tid & 31) == 0) sw[tid >> 5] = f;
    __syncthreads();
    float npos = sw[0] + sw[1];
    __syncthreads();

    const float LOG_T = 4.852030263919617f;    // ln(128)
    float contrib = 0.0f;
    if (tid < NSLOT) {
        float w = (tid == 0) ? ((float)TT - npos) : wpos;
        if (w != 0.0f) contrib = w * (__logf(total) - LOG_T);
    }
#pragma unroll
    for (int o = 16; o > 0; o >>= 1)
        contrib += __shfl_xor_sync(0xFFFFFFFFu, contrib, o);
    if ((tid & 31) == 0) sw[tid >> 5] = contrib;
    __syncthreads();
    if (tid == 0)
        atomicAdd(out, -(sw[0] + sw[1]) * (1.0f / ((float)BB * (float)TT)));
}

extern "C" void kernel_launch(void* const* d_in, const int* in_sizes, int n_in,
                              void* d_out, int out_size)
{
    const float*     preds = (const float*)d_in[0];
    const long long* tgt   = (const long long*)d_in[1];
    float*           out   = (float*)d_out;

    zsum_kernel<<<64 * BB, 256>>>(preds, tgt, out);
    finish_kernel<<<BB, 64>>>(out);
}

// round 10
// speedup vs baseline: 1.0681x; 1.0255x over previous
#include <cuda_runtime.h>
#include <cuda_bf16.h>
#include <cstdint>

// Problem shape (fixed by setup_inputs): preds [T,B,C] f32, targets [B,L] i64.
#define TT 128
#define BB 128
#define CC 8192
#define LL 50
#define NSLOT 51   // slot 0 = blank, slots 1..50 = labels

// Dense accumulator: g_acc[b][slot] = sum_t exp(x[t,b,c_slot])/Z[t,b].
// Zero at module load; finish_kernel re-zeroes after reading -> invariant
// holds across graph replays. 26 KB, L2-resident.
__device__ float g_acc[BB * NSLOT];

// Fast exp on the FMA pipe (no MUFU). Rel err ~5e-5.
__device__ __forceinline__ float fast_exp(float x) {
    const float L2E = 1.4426950408889634f;
    float t  = fmaf(x, L2E, 12582912.0f);
    float nf = t - 12582912.0f;
    float f  = fmaf(x, L2E, -nf);
    int   ni = __float_as_int(t) - 0x4B400000;
    float sc = __int_as_float((ni << 23) + 0x3F800000);
    float p = fmaf(f, 0.009618129f, 0.05550411f);
    p = fmaf(f, p, 0.2402265f);
    p = fmaf(f, p, 0.6931472f);
    float fp = f * p;
    return fmaf(fp, sc, sc);
}

// ---------------------------------------------------------------------------
// Kernel 1: one block per (t,b) row.
//   1. load label c (L2-hot after first wave)
//   2. issue the sparse gather LDG x_c IMMEDIATELY (latency hidden by step 3)
//   3. stream 32 KB -> Z
//   4. reduce; REDG fast_exp(x_c)/Z into dense g_acc[b][slot]
// The block tail has no exposed memory latency.
// ---------------------------------------------------------------------------
__global__ __launch_bounds__(256) void zsum_kernel(
    const float* __restrict__ preds,
    const long long* __restrict__ tgt,
    float* __restrict__ out)
{
    int tb  = blockIdx.x;                 // = t*BB + b
    int b   = tb & (BB - 1);
    int tid = threadIdx.x;
    if (tb == 0 && tid == 0) *out = 0.0f;

    const float* rowf = preds + (size_t)tb * CC;

    // Step 1+2: label, then fire the sparse gather right away.
    int c = 0;                            // slot 0 -> blank class 0
    if (tid >= 1 && tid < NSLOT) {
        long long l = tgt[(size_t)b * LL + (tid - 1)];
        if (l > 0 && l < CC) c = (int)l;  // invalid -> class 0 (weight 0 later)
    }
    float xc = 0.0f;
    if (tid < NSLOT) xc = __ldg(rowf + c);   // in flight during the stream

    // Step 3: stream the row.
    const float4* row = reinterpret_cast<const float4*>(rowf);
    float acc = 0.0f;
#pragma unroll
    for (int i = 0; i < 8; i++) {
        float4 v = row[tid + i * 256];    // 8 front-batched LDG.128
        acc += fast_exp(v.x) + fast_exp(v.y) + fast_exp(v.z) + fast_exp(v.w);
    }
#pragma unroll
    for (int o = 16; o > 0; o >>= 1)
        acc += __shfl_xor_sync(0xFFFFFFFFu, acc, o);

    __shared__ float s[8];
    if ((tid & 31) == 0) s[tid >> 5] = acc;
    __syncthreads();

    // Step 4: tail with zero exposed memory latency.
    if (tid < NSLOT) {
        float z = s[0] + s[1] + s[2] + s[3] + s[4] + s[5] + s[6] + s[7];
        atomicAdd(&g_acc[b * NSLOT + tid], fast_exp(xc) * (1.0f / z));
    }
}

// ---------------------------------------------------------------------------
// Kernel 2: tiny. One block per b, 64 threads. Read the 51 accumulated sums
// (L2-hot), weights from targets, logs, atomicAdd into out, re-zero g_acc.
// ---------------------------------------------------------------------------
__global__ __launch_bounds__(64) void finish_kernel(
    const long long* __restrict__ tgt,
    float* __restrict__ out)
{
    int b   = blockIdx.x;
    int tid = threadIdx.x;

    float total = 0.0f;
    float wpos  = 0.0f;
    if (tid < NSLOT) {
        total = g_acc[b * NSLOT + tid];
        g_acc[b * NSLOT + tid] = 0.0f;     // restore invariant for next replay
        if (tid >= 1) {
            long long l = tgt[(size_t)b * LL + (tid - 1)];
            wpos = (l > 0 && l < CC) ? 1.0f : 0.0f;
        }
    }

    // npos = sum of wpos over the block (2 warps).
    __shared__ float sw[2];
    float f = wpos;
#pragma unroll
    for (int o = 16; o > 0; o >>= 1)
        f += __shfl_xor_sync(0xFFFFFFFFu, f, o);
    if ((tid & 31) == 0) sw[tid >> 5] = f;
    __syncthreads();
    float npos = sw[0] + sw[1];
    __syncthreads();

    const float LOG_T = 4.852030263919617f;    // ln(128)
    float contrib = 0.0f;
    if (tid < NSLOT) {
        float w = (tid == 0) ? ((float)TT - npos) : wpos;
        if (w != 0.0f) contrib = w * (__logf(total) - LOG_T);
    }
#pragma unroll
    for (int o = 16; o > 0; o >>= 1)
        contrib += __shfl_xor_sync(0xFFFFFFFFu, contrib, o);
    if ((tid & 31) == 0) sw[tid >> 5] = contrib;
    __syncthreads();
    if (tid == 0)
        atomicAdd(out, -(sw[0] + sw[1]) * (1.0f / ((float)BB * (float)TT)));
}

extern "C" void kernel_launch(void* const* d_in, const int* in_sizes, int n_in,
                              void* d_out, int out_size)
{
    const float*     preds = (const float*)d_in[0];
    const long long* tgt   = (const long long*)d_in[1];
    float*           out   = (float*)d_out;

    zsum_kernel<<<TT * BB, 256>>>(preds, tgt, out);
    finish_kernel<<<BB, 64>>>(tgt, out);
}